// round 14
// baseline (speedup 1.0000x reference)
#include <cuda_runtime.h>
#include <cstdint>

#define LRELU(v) ((v) > 0.0f ? (v) : 0.01f * (v))
using ull = unsigned long long;

static constexpr int Bb   = 512;
static constexpr int Nn   = 64;
static constexpr int Hh   = 4;
static constexpr int FOUT = 16;

// Scratch
__device__ float g_x1[(size_t)Bb * Nn * 128];
__device__ float g_x2[(size_t)Bb * Nn * 128];
__device__ float g_M [(size_t)2 * Hh * 128 * 128];   // M_h = Qw^T Kw ([d'][d])
__device__ float g_a2[(size_t)2 * Hh * 128];         // a2_h = Kw^T qb

// ---------------------------------------------------------------------------
// Packed fp32x2 helpers
// ---------------------------------------------------------------------------
__device__ __forceinline__ ull pack2(float a, float b) {
    ull r; asm("mov.b64 %0, {%1, %2};" : "=l"(r) : "f"(a), "f"(b)); return r;
}
__device__ __forceinline__ void unpack2(ull v, float& a, float& b) {
    asm("mov.b64 {%0, %1}, %2;" : "=f"(a), "=f"(b) : "l"(v));
}
__device__ __forceinline__ ull fma2(ull a, ull b, ull c) {
    ull d; asm("fma.rn.f32x2 %0, %1, %2, %3;" : "=l"(d) : "l"(a), "l"(b), "l"(c)); return d;
}

// ---------------------------------------------------------------------------
// cp.async helpers
// ---------------------------------------------------------------------------
__device__ __forceinline__ uint32_t s2u(const void* p) {
    return (uint32_t)__cvta_generic_to_shared(p);
}
__device__ __forceinline__ void cp4(uint32_t dst, const float* src) {
    asm volatile("cp.async.ca.shared.global [%0], [%1], 4;" :: "r"(dst), "l"(src));
}
__device__ __forceinline__ void cp_commit() {
    asm volatile("cp.async.commit_group;" ::: "memory");
}
template<int N>
__device__ __forceinline__ void cp_wait() {
    asm volatile("cp.async.wait_group %0;" :: "n"(N) : "memory");
}

// ---------------------------------------------------------------------------
// Prep: per head, M[d'][d] = sum_e Kw[e,d']*Qw[e,d] ;  a2[d] = sum_e Kw[e,d]*qb[e]
// ---------------------------------------------------------------------------
__global__ void __launch_bounds__(256)
prep_kernel(const float* __restrict__ Qw, const float* __restrict__ Kw,
            const float* __restrict__ Qb, float* __restrict__ Mout,
            float* __restrict__ a2out)
{
    const int h = blockIdx.x, slice = blockIdx.y, tid = threadIdx.x;
    const float* Qh = Qw + (size_t)h * 128 * 128;
    const float* Kh = Kw + (size_t)h * 128 * 128;
#pragma unroll
    for (int j = 0; j < 8; ++j) {
        int id = tid + 256 * j;
        int dp = 16 * slice + (id >> 7);
        int d  = id & 127;
        float s = 0.f;
#pragma unroll 4
        for (int e = 0; e < 128; ++e)
            s += __ldg(&Kh[e * 128 + dp]) * __ldg(&Qh[e * 128 + d]);
        Mout[((size_t)h * 128 + dp) * 128 + d] = s;
    }
    if (slice == 0 && tid < 128) {
        float s = 0.f;
#pragma unroll 4
        for (int e = 0; e < 128; ++e)
            s += __ldg(&Kh[e * 128 + tid]) * __ldg(&Qb[h * 128 + e]);
        a2out[h * 128 + tid] = s;
    }
}

// ---------------------------------------------------------------------------
// smem layout (103.2 KB -> 2 CTAs/SM):
//   s_xt  [32][68]   streamed x k-tile (transposed); 2b staging buf1
//   s_seT [128][68]  se^T (stride 68: float4-aligned rows)
//   s_t   [64][128]  t = se M^T; staging buf1 for phases 1 & 2a
//   s_wt  [128*36]   staging buf0; s_w overlay in phases 3/4
//   s_v   [64][32]
//   s_c   [64]
// ---------------------------------------------------------------------------
static constexpr int OFF_XT  = 0;
static constexpr int OFF_SET = OFF_XT  + 32 * 68;     // 2176
static constexpr int OFF_T   = OFF_SET + 128 * 68;    // +8704
static constexpr int OFF_WT  = OFF_T   + 64 * 128;    // +8192
static constexpr int OFF_V   = OFF_WT  + 128 * 36;    // +4608
static constexpr int OFF_C   = OFF_V   + 64 * 32;     // +2048
static constexpr int SMEM_FLOATS = OFF_C + 64;        // 25792 -> 103168 B

template<int IN_DIM>
__global__ void __launch_bounds__(256, 2)
attn_kernel(const float* __restrict__ x,
            const float* __restrict__ Ew, const float* __restrict__ Eb,
            const float* __restrict__ gM, const float* __restrict__ gA2,
            const float* __restrict__ Vw, const float* __restrict__ Vb,
            float* __restrict__ w_out, float* __restrict__ x_out)
{
    extern __shared__ float smem[];
    float* s_xt  = smem + OFF_XT;
    float* s_seT = smem + OFF_SET;
    float* s_t   = smem + OFF_T;
    float* s_wt  = smem + OFF_WT;
    float* s_v   = smem + OFF_V;
    float* s_c   = smem + OFF_C;
    float* s_w   = s_wt;                 // overlay in phases 3/4

    const int h = blockIdx.x, b = blockIdx.y, tid = threadIdx.x;
    const float* gx  = x + (size_t)b * 64 * IN_DIM;
    const float* Ewh = Ew + (size_t)h * 128 * IN_DIM;

    // ---- Phase 1: seT[d][n] = lrelu(x Ew^T + Eb)^T ------------------------
    {
        const int tx = tid & 15, ty = tid >> 4;     // 16 n-quads x 16 d-groups
        ull acc[8][2] = {};
        float rx[8];
        float* ebuf[2] = { s_wt, s_t };             // double-buffered E staging
        auto ldx = [&](int t) {
#pragma unroll
            for (int j = 0; j < 8; ++j) {
                int idx = tid + 256 * j;
                rx[j] = __ldg(&gx[(idx >> 5) * IN_DIM + t * 32 + (idx & 31)]);
            }
        };
        auto stx = [&]() {
#pragma unroll
            for (int j = 0; j < 8; ++j) {
                int idx = tid + 256 * j;
                s_xt[(idx & 31) * 68 + (idx >> 5)] = rx[j];
            }
        };
        auto stageE = [&](int t, float* dst0) {
            for (int idx = tid; idx < 4096; idx += 256) {
                int d = idx >> 5, kk = idx & 31;
                cp4(s2u(dst0 + d * 36 + kk), Ewh + (size_t)d * IN_DIM + t * 32 + kk);
            }
            cp_commit();
        };
        ldx(0); stageE(0, ebuf[0]);
        const int NT = IN_DIM / 32;
        for (int t = 0; t < NT; ++t) {
            if (t + 1 < NT) { stageE(t + 1, ebuf[(t + 1) & 1]); cp_wait<1>(); }
            else            { cp_wait<0>(); }
            __syncthreads();                        // E tile t ready; s_xt free
            stx();
            if (t + 1 < NT) ldx(t + 1);
            __syncthreads();                        // x tile visible
            const float* w = ebuf[t & 1];
#pragma unroll
            for (int k4 = 0; k4 < 8; ++k4) {
                float4 a[8];
#pragma unroll
                for (int r = 0; r < 8; ++r)
                    a[r] = *(const float4*)&w[(8 * ty + r) * 36 + 4 * k4];
#pragma unroll
                for (int q = 0; q < 4; ++q) {
                    ulonglong2 bb = *(const ulonglong2*)&s_xt[(4 * k4 + q) * 68 + 4 * tx];
#pragma unroll
                    for (int r = 0; r < 8; ++r) {
                        ull ap = pack2((&a[r].x)[q], (&a[r].x)[q]);
                        acc[r][0] = fma2(ap, bb.x, acc[r][0]);
                        acc[r][1] = fma2(ap, bb.y, acc[r][1]);
                    }
                }
            }
            __syncthreads();                        // frees buffers for t+2 / stx
        }
#pragma unroll
        for (int r = 0; r < 8; ++r) {
            int d = 8 * ty + r;
            float bias = __ldg(&Eb[h * 128 + d]);
            float v0, v1, v2, v3;
            unpack2(acc[r][0], v0, v1); unpack2(acc[r][1], v2, v3);
            v0 += bias; v1 += bias; v2 += bias; v3 += bias;
            v0 = LRELU(v0); v1 = LRELU(v1); v2 = LRELU(v2); v3 = LRELU(v3);
            float4 sv = make_float4(v0, v1, v2, v3);
            *(float4*)&s_seT[d * 68 + 4 * tx] = sv;
        }
    }

    // ---- Phase 2a: t[n][d'] = se M^T --------------------------------------
    {
        const int tx = tid & 31, ty = tid >> 5;     // 32 d'-quads x 8 n-groups
        ull acc[8][2] = {};
        const float* gMh = gM + (size_t)h * 128 * 128;
        float* mbuf[2] = { s_wt, s_t };             // s_t free until epilogue
        auto stageM = [&](int t, float* dst0) {
            for (int idx = tid; idx < 4096; idx += 256) {
                int n = idx >> 5, kk = idx & 31;
                cp4(s2u(dst0 + kk * 132 + n), gMh + (size_t)n * 128 + t * 32 + kk);
            }
            cp_commit();
        };
        stageM(0, mbuf[0]);
        for (int t = 0; t < 4; ++t) {
            if (t + 1 < 4) { stageM(t + 1, mbuf[(t + 1) & 1]); cp_wait<1>(); }
            else           { cp_wait<0>(); }
            __syncthreads();                        // tile ready; orders seT too
            const float* w = mbuf[t & 1];
#pragma unroll
            for (int k4 = 0; k4 < 8; ++k4) {
#pragma unroll
                for (int q = 0; q < 4; ++q) {
                    int row = t * 32 + 4 * k4 + q;
                    float4 sa0 = *(const float4*)&s_seT[row * 68 + 8 * ty];
                    float4 sa1 = *(const float4*)&s_seT[row * 68 + 8 * ty + 4];
                    ulonglong2 bb = *(const ulonglong2*)&w[(4 * k4 + q) * 132 + 4 * tx];
#pragma unroll
                    for (int r = 0; r < 4; ++r) {
                        ull ap = pack2((&sa0.x)[r], (&sa0.x)[r]);
                        acc[r][0] = fma2(ap, bb.x, acc[r][0]);
                        acc[r][1] = fma2(ap, bb.y, acc[r][1]);
                    }
#pragma unroll
                    for (int r = 0; r < 4; ++r) {
                        ull ap = pack2((&sa1.x)[r], (&sa1.x)[r]);
                        acc[4 + r][0] = fma2(ap, bb.x, acc[4 + r][0]);
                        acc[4 + r][1] = fma2(ap, bb.y, acc[4 + r][1]);
                    }
                }
            }
            __syncthreads();
        }
#pragma unroll
        for (int r = 0; r < 8; ++r) {
            int row = 8 * ty + r;
            float v0, v1, v2, v3;
            unpack2(acc[r][0], v0, v1); unpack2(acc[r][1], v2, v3);
            *(float4*)&s_t[row * 128 + 4 * tx] = make_float4(v0, v1, v2, v3);
        }
    }

    // ---- Phase 2b: v[m][o] = lrelu(se Vw^T + Vb) ---------------------------
    {
        const int tx = tid & 15, ty = tid >> 4;     // 16 o-pairs x 16 m-groups
        ull acc[4] = {};
        const float* Vwh = Vw + (size_t)h * 32 * 128;
        float* vbuf[2] = { s_wt, s_xt };            // compact stride 36
        auto stageV = [&](int t, float* dst0) {
            for (int idx = tid; idx < 1024; idx += 256) {
                int n = idx >> 5, kk = idx & 31;
                cp4(s2u(dst0 + kk * 36 + n), Vwh + (size_t)n * 128 + t * 32 + kk);
            }
            cp_commit();
        };
        stageV(0, vbuf[0]);
        for (int t = 0; t < 4; ++t) {
            if (t + 1 < 4) { stageV(t + 1, vbuf[(t + 1) & 1]); cp_wait<1>(); }
            else           { cp_wait<0>(); }
            __syncthreads();
            const float* w = vbuf[t & 1];
#pragma unroll
            for (int k4 = 0; k4 < 8; ++k4) {
#pragma unroll
                for (int q = 0; q < 4; ++q) {
                    int row = t * 32 + 4 * k4 + q;
                    float4 sa = *(const float4*)&s_seT[row * 68 + 4 * ty];
                    ull bb = *(const ull*)&w[(4 * k4 + q) * 36 + 2 * tx];
#pragma unroll
                    for (int r = 0; r < 4; ++r)
                        acc[r] = fma2(pack2((&sa.x)[r], (&sa.x)[r]), bb, acc[r]);
                }
            }
            __syncthreads();
        }
        float b0 = __ldg(&Vb[h * 32 + 2 * tx]), b1 = __ldg(&Vb[h * 32 + 2 * tx + 1]);
#pragma unroll
        for (int r = 0; r < 4; ++r) {
            float v0, v1; unpack2(acc[r], v0, v1);
            v0 += b0; v1 += b1; v0 = LRELU(v0); v1 = LRELU(v1);
            *(float2*)&s_v[(4 * ty + r) * 32 + 2 * tx] = make_float2(v0, v1);
        }
    }

    // ---- c_m = se_m . a2 ----------------------------------------------------
    if (tid < 64) {
        const float* a2h = gA2 + h * 128;
        float s = 0.f;
#pragma unroll 4
        for (int d = 0; d < 128; ++d)
            s += s_seT[d * 68 + tid] * __ldg(&a2h[d]);
        s_c[tid] = s;
    }
    __syncthreads();

    // ---- Phase 3: scores = t . seT + c, softmax ----------------------------
    {
        const int tx = tid & 31, ty = tid >> 5;
        const float2 cc = *(const float2*)&s_c[2 * tx];
        ull sacc[8] = {};
#pragma unroll 4
        for (int k4 = 0; k4 < 32; ++k4) {
            float4 a[8];
#pragma unroll
            for (int r = 0; r < 8; ++r)
                a[r] = *(const float4*)&s_t[(8 * ty + r) * 128 + 4 * k4];
#pragma unroll
            for (int q = 0; q < 4; ++q) {
                ull bb = *(const ull*)&s_seT[(4 * k4 + q) * 68 + 2 * tx];
#pragma unroll
                for (int r = 0; r < 8; ++r)
                    sacc[r] = fma2(pack2((&a[r].x)[q], (&a[r].x)[q]), bb, sacc[r]);
            }
        }
        const float SCALE = 0.08838834764831845f;   // 1/sqrt(128)
        float* wg = w_out + (((size_t)h * Bb + b) * 64) * 64;
#pragma unroll
        for (int i = 0; i < 8; ++i) {
            float sc0, sc1; unpack2(sacc[i], sc0, sc1);
            sc0 = (sc0 + cc.x) * SCALE;
            sc1 = (sc1 + cc.y) * SCALE;
            float m = fmaxf(sc0, sc1);
#pragma unroll
            for (int off = 1; off < 32; off <<= 1)
                m = fmaxf(m, __shfl_xor_sync(0xffffffffu, m, off));
            sc0 = __expf(sc0 - m); sc1 = __expf(sc1 - m);
            float s = sc0 + sc1;
#pragma unroll
            for (int off = 1; off < 32; off <<= 1)
                s += __shfl_xor_sync(0xffffffffu, s, off);
            float inv = 1.0f / s;
            float2 wv = make_float2(sc0 * inv, sc1 * inv);
            int row = 8 * ty + i;
            *(float2*)&s_w[row * 64 + 2 * tx] = wv;
            *(float2*)&wg[(size_t)row * 64 + 2 * tx] = wv;
        }
    }
    __syncthreads();

    // ---- Phase 4: att = w @ v ----------------------------------------------
    {
        const int tx = tid & 15, ty = tid >> 4;
        ull aacc[4] = {};
#pragma unroll 4
        for (int k4 = 0; k4 < 16; ++k4) {
            float4 a0 = *(const float4*)&s_w[(4 * ty + 0) * 64 + 4 * k4];
            float4 a1 = *(const float4*)&s_w[(4 * ty + 1) * 64 + 4 * k4];
            float4 a2 = *(const float4*)&s_w[(4 * ty + 2) * 64 + 4 * k4];
            float4 a3 = *(const float4*)&s_w[(4 * ty + 3) * 64 + 4 * k4];
#pragma unroll
            for (int q = 0; q < 4; ++q) {
                ull bb = *(const ull*)&s_v[(4 * k4 + q) * 32 + 2 * tx];
                aacc[0] = fma2(pack2((&a0.x)[q], (&a0.x)[q]), bb, aacc[0]);
                aacc[1] = fma2(pack2((&a1.x)[q], (&a1.x)[q]), bb, aacc[1]);
                aacc[2] = fma2(pack2((&a2.x)[q], (&a2.x)[q]), bb, aacc[2]);
                aacc[3] = fma2(pack2((&a3.x)[q], (&a3.x)[q]), bb, aacc[3]);
            }
        }
#pragma unroll
        for (int i = 0; i < 4; ++i) {
            float v0, v1; unpack2(aacc[i], v0, v1);
            int row = 4 * ty + i;
            *(float2*)&x_out[((size_t)b * 64 + row) * 128 + h * 32 + 2 * tx] =
                make_float2(v0, v1);
        }
    }
}

// ---------------------------------------------------------------------------
// Final MLP + softmax policy head.
// ---------------------------------------------------------------------------
__global__ void __launch_bounds__(256)
mlp_kernel(const float* __restrict__ x,
           const float* __restrict__ F1w, const float* __restrict__ F1b,
           const float* __restrict__ F2w, const float* __restrict__ F2b,
           float* __restrict__ out)
{
    __shared__ float sF1[128 * 65];
    __shared__ float sF2[16 * 64];
    __shared__ float sB1[64];
    __shared__ float sB2[16];
    __shared__ float sx[8][2][128];

    const int tid = threadIdx.x, lane = tid & 31, warp = tid >> 5;

    for (int idx = tid; idx < 64 * 128; idx += 256) {
        int o = idx >> 7, d = idx & 127;
        sF1[d * 65 + o] = F1w[idx];
    }
    for (int idx = tid; idx < 16 * 64; idx += 256) sF2[idx] = F2w[idx];
    if (tid < 64) sB1[tid] = F1b[tid];
    if (tid < 16) sB2[tid] = F2b[tid];
    __syncthreads();

    const int NGRP = (Bb * Nn) / 2;
    for (int g = blockIdx.x * 8 + warp; g < NGRP; g += gridDim.x * 8) {
        int row0 = g * 2;
#pragma unroll
        for (int r = 0; r < 2; ++r)
            *(float4*)&sx[warp][r][lane * 4] =
                *(const float4*)&x[(size_t)(row0 + r) * 128 + lane * 4];
        __syncwarp();

        float h0[2], h1[2];
        h0[0] = h0[1] = sB1[lane];
        h1[0] = h1[1] = sB1[lane + 32];
#pragma unroll 8
        for (int d = 0; d < 128; ++d) {
            float w0 = sF1[d * 65 + lane];
            float w1 = sF1[d * 65 + 32 + lane];
#pragma unroll
            for (int r = 0; r < 2; ++r) {
                float xv = sx[warp][r][d];
                h0[r] = fmaf(xv, w0, h0[r]);
                h1[r] = fmaf(xv, w1, h1[r]);
            }
        }
#pragma unroll
        for (int r = 0; r < 2; ++r) { h0[r] = LRELU(h0[r]); h1[r] = LRELU(h1[r]); }

#pragma unroll
        for (int r = 0; r < 2; ++r) {
            float p[16];
#pragma unroll
            for (int j = 0; j < 16; ++j) {
                float t = fmaf(h0[r], sF2[j * 64 + lane],
                               h1[r] * sF2[j * 64 + 32 + lane]);
#pragma unroll
                for (int off = 16; off > 0; off >>= 1)
                    t += __shfl_xor_sync(0xffffffffu, t, off);
                p[j] = t + sB2[j];
            }
            float m = p[0];
#pragma unroll
            for (int j = 1; j < 16; ++j) m = fmaxf(m, p[j]);
            float s = 0.0f;
#pragma unroll
            for (int j = 0; j < 16; ++j) { p[j] = __expf(p[j] - m); s += p[j]; }
            float inv = 1.0f / s;
            float mine = 0.0f;
#pragma unroll
            for (int j = 0; j < 16; ++j) mine = (lane == j) ? p[j] * inv : mine;
            if (lane < 16) out[(size_t)(row0 + r) * 16 + lane] = mine;
        }
        __syncwarp();
    }
}

// ---------------------------------------------------------------------------
extern "C" void kernel_launch(void* const* d_in, const int* in_sizes, int n_in,
                              void* d_out, int out_size)
{
    const float* states = (const float*)d_in[0];
    const float* E1w = (const float*)d_in[1];  const float* E1b = (const float*)d_in[2];
    const float* K1w = (const float*)d_in[3];  const float* K1b = (const float*)d_in[4];
    const float* Q1w = (const float*)d_in[5];  const float* Q1b = (const float*)d_in[6];
    const float* V1w = (const float*)d_in[7];  const float* V1b = (const float*)d_in[8];
    const float* E2w = (const float*)d_in[9];  const float* E2b = (const float*)d_in[10];
    const float* K2w = (const float*)d_in[11]; const float* K2b = (const float*)d_in[12];
    const float* Q2w = (const float*)d_in[13]; const float* Q2b = (const float*)d_in[14];
    const float* V2w = (const float*)d_in[15]; const float* V2b = (const float*)d_in[16];
    const float* F1w = (const float*)d_in[17]; const float* F1b = (const float*)d_in[18];
    const float* F2w = (const float*)d_in[19]; const float* F2b = (const float*)d_in[20];
    (void)K1b; (void)K2b;   // K biases cancel in softmax

    float* out    = (float*)d_out;
    float* policy = out;                                      // [512,64,16]
    float* w1     = out + (size_t)Bb * Nn * FOUT;             // [4,512,64,64]
    float* w2     = w1 + (size_t)Hh * Bb * Nn * Nn;           // [4,512,64,64]

    float* x1p = nullptr; float* x2p = nullptr;
    float* Mp = nullptr;  float* a2p = nullptr;
    cudaGetSymbolAddress((void**)&x1p, g_x1);
    cudaGetSymbolAddress((void**)&x2p, g_x2);
    cudaGetSymbolAddress((void**)&Mp,  g_M);
    cudaGetSymbolAddress((void**)&a2p, g_a2);

    prep_kernel<<<dim3(Hh, 8), 256>>>(Q1w, K1w, Q1b, Mp,                  a2p);
    prep_kernel<<<dim3(Hh, 8), 256>>>(Q2w, K2w, Q2b, Mp + Hh * 128 * 128, a2p + Hh * 128);

    const int SMEM = SMEM_FLOATS * 4;   // 103168 B -> 2 CTAs/SM
    cudaFuncSetAttribute(attn_kernel<256>, cudaFuncAttributeMaxDynamicSharedMemorySize, SMEM);
    cudaFuncSetAttribute(attn_kernel<128>, cudaFuncAttributeMaxDynamicSharedMemorySize, SMEM);

    dim3 grid(Hh, Bb);
    attn_kernel<256><<<grid, 256, SMEM>>>(states, E1w, E1b,
                                          Mp, a2p, V1w, V1b, w1, x1p);
    attn_kernel<128><<<grid, 256, SMEM>>>(x1p, E2w, E2b,
                                          Mp + Hh * 128 * 128, a2p + Hh * 128,
                                          V2w, V2b, w2, x2p);
    mlp_kernel<<<512, 256>>>(x2p, F1w, F1b, F2w, F2b, policy);
}

// round 15
// speedup vs baseline: 1.1655x; 1.1655x over previous
#include <cuda_runtime.h>
#include <cstdint>

#define LRELU(v) ((v) > 0.0f ? (v) : 0.01f * (v))
using ull = unsigned long long;

static constexpr int Bb   = 512;
static constexpr int Nn   = 64;
static constexpr int Hh   = 4;
static constexpr int FOUT = 16;

// Scratch
__device__ float g_x1[(size_t)Bb * Nn * 128];
__device__ float g_x2[(size_t)Bb * Nn * 128];
__device__ float g_M  [(size_t)2 * Hh * 128 * 128];  // M^T_h: [d][d'] (pre-transposed)
__device__ float g_a2 [(size_t)2 * Hh * 128];        // a2_h = Kw^T qb
__device__ float g_VwT[(size_t)2 * Hh * 128 * 32];   // Vw^T_h: [k][o]

// ---------------------------------------------------------------------------
// Packed fp32x2 helpers
// ---------------------------------------------------------------------------
__device__ __forceinline__ ull pack2(float a, float b) {
    ull r; asm("mov.b64 %0, {%1, %2};" : "=l"(r) : "f"(a), "f"(b)); return r;
}
__device__ __forceinline__ void unpack2(ull v, float& a, float& b) {
    asm("mov.b64 {%0, %1}, %2;" : "=f"(a), "=f"(b) : "l"(v));
}
__device__ __forceinline__ ull fma2(ull a, ull b, ull c) {
    ull d; asm("fma.rn.f32x2 %0, %1, %2, %3;" : "=l"(d) : "l"(a), "l"(b), "l"(c)); return d;
}

// ---------------------------------------------------------------------------
// cp.async helpers
// ---------------------------------------------------------------------------
__device__ __forceinline__ uint32_t s2u(const void* p) {
    return (uint32_t)__cvta_generic_to_shared(p);
}
__device__ __forceinline__ void cp16(uint32_t dst, const float* src) {
    asm volatile("cp.async.cg.shared.global [%0], [%1], 16;" :: "r"(dst), "l"(src));
}
__device__ __forceinline__ void cp_commit() {
    asm volatile("cp.async.commit_group;" ::: "memory");
}
template<int N>
__device__ __forceinline__ void cp_wait() {
    asm volatile("cp.async.wait_group %0;" :: "n"(N) : "memory");
}

// ---------------------------------------------------------------------------
// Prep per head: M^T[d][d'] = sum_e Kw[e,d']*Qw[e,d];  a2[d] = sum_e Kw[e,d]*qb[e];
//                Vw^T[k][o] = Vw[o][k].
// grid (4 heads, 8 slices), 256 threads.
// ---------------------------------------------------------------------------
__global__ void __launch_bounds__(256)
prep_kernel(const float* __restrict__ Qw, const float* __restrict__ Kw,
            const float* __restrict__ Qb, const float* __restrict__ Vw,
            float* __restrict__ Mout, float* __restrict__ a2out,
            float* __restrict__ VwTout)
{
    const int h = blockIdx.x, slice = blockIdx.y, tid = threadIdx.x;
    const float* Qh = Qw + (size_t)h * 128 * 128;
    const float* Kh = Kw + (size_t)h * 128 * 128;
#pragma unroll
    for (int j = 0; j < 8; ++j) {
        int id = tid + 256 * j;
        int d  = 16 * slice + (id >> 7);     // warp-uniform (Q side)
        int dp = id & 127;                   // lane-consecutive (K side)
        float s = 0.f;
#pragma unroll 4
        for (int e = 0; e < 128; ++e)
            s += __ldg(&Kh[e * 128 + dp]) * __ldg(&Qh[e * 128 + d]);
        Mout[((size_t)h * 128 + d) * 128 + dp] = s;     // transposed layout
    }
    if (slice == 0 && tid < 128) {
        float s = 0.f;
#pragma unroll 4
        for (int e = 0; e < 128; ++e)
            s += __ldg(&Kh[e * 128 + tid]) * __ldg(&Qb[h * 128 + e]);
        a2out[h * 128 + tid] = s;
    }
    if (slice == 1) {
        const float* Vh = Vw + (size_t)h * 32 * 128;
        for (int idx = tid; idx < 128 * 32; idx += 256) {
            int k = idx >> 5, o = idx & 31;
            VwTout[(size_t)h * 128 * 32 + idx] = __ldg(&Vh[o * 128 + k]);
        }
    }
}

// ---------------------------------------------------------------------------
// smem layout (102.1 KB -> 2 CTAs/SM)  [identical to R13]
// ---------------------------------------------------------------------------
static constexpr int OFF_XT  = 0;                     // [32][68]
static constexpr int OFF_SET = OFF_XT  + 32 * 68;     // [128][66]
static constexpr int OFF_T   = OFF_SET + 128 * 66;    // [64][128]
static constexpr int OFF_WT  = OFF_T   + 64 * 128;    // 128*36 staging / s_w overlay
static constexpr int OFF_V   = OFF_WT  + 128 * 36;    // [64][32]
static constexpr int OFF_C   = OFF_V   + 64 * 32;     // [64]
static constexpr int SMEM_FLOATS = OFF_C + 64;        // 25536 -> 102144 B

template<int IN_DIM>
__global__ void __launch_bounds__(256, 2)
attn_kernel(const float* __restrict__ x,
            const float* __restrict__ Ew, const float* __restrict__ Eb,
            const float* __restrict__ gM, const float* __restrict__ gA2,
            const float* __restrict__ gVwT, const float* __restrict__ Vb,
            float* __restrict__ w_out, float* __restrict__ x_out)
{
    extern __shared__ float smem[];
    float* s_xt  = smem + OFF_XT;
    float* s_seT = smem + OFF_SET;
    float* s_t   = smem + OFF_T;
    float* s_wt  = smem + OFF_WT;
    float* s_v   = smem + OFF_V;
    float* s_c   = smem + OFF_C;
    float* s_w   = s_wt;                 // overlay in phases 3/4

    const int h = blockIdx.x, b = blockIdx.y, tid = threadIdx.x;
    const float* gx  = x + (size_t)b * 64 * IN_DIM;
    const float* Ewh = Ew + (size_t)h * 128 * IN_DIM;

    // ---- Phase 1: seT[d][n] = lrelu(x Ew^T + Eb)^T ------------------------
    {
        const int tx = tid & 15, ty = tid >> 4;     // 16 n-quads x 16 d-groups
        ull acc[8][2] = {};
        float4 rx[2];
        auto ldx = [&](int t) {
#pragma unroll
            for (int j = 0; j < 2; ++j) {
                int idx = tid + 256 * j;
                rx[j] = *(const float4*)&gx[(idx >> 3) * IN_DIM + t * 32 + (idx & 7) * 4];
            }
        };
        auto stx = [&]() {
#pragma unroll
            for (int j = 0; j < 2; ++j) {
                int idx = tid + 256 * j, n = idx >> 3, c = idx & 7;
                s_xt[(c * 4 + 0) * 68 + n] = rx[j].x;
                s_xt[(c * 4 + 1) * 68 + n] = rx[j].y;
                s_xt[(c * 4 + 2) * 68 + n] = rx[j].z;
                s_xt[(c * 4 + 3) * 68 + n] = rx[j].w;
            }
        };
        auto stageE = [&](int t) {
            for (int idx = tid; idx < 1024; idx += 256) {
                int d = idx >> 3, c = idx & 7;
                cp16(s2u(s_wt + d * 36 + c * 4),
                     Ewh + (size_t)d * IN_DIM + t * 32 + c * 4);
            }
            cp_commit();
        };
        ldx(0); stageE(0);
        const int NT = IN_DIM / 32;
        for (int t = 0; t < NT; ++t) {
            cp_wait<0>(); __syncthreads();          // E tile ready, s_xt free
            stx();
            if (t + 1 < NT) ldx(t + 1);
            __syncthreads();                        // x tile visible
#pragma unroll
            for (int k4 = 0; k4 < 8; ++k4) {
                float4 a[8];
#pragma unroll
                for (int r = 0; r < 8; ++r)
                    a[r] = *(const float4*)&s_wt[(8 * ty + r) * 36 + 4 * k4];
#pragma unroll
                for (int q = 0; q < 4; ++q) {
                    ulonglong2 bb = *(const ulonglong2*)&s_xt[(4 * k4 + q) * 68 + 4 * tx];
#pragma unroll
                    for (int r = 0; r < 8; ++r) {
                        ull ap = pack2((&a[r].x)[q], (&a[r].x)[q]);
                        acc[r][0] = fma2(ap, bb.x, acc[r][0]);
                        acc[r][1] = fma2(ap, bb.y, acc[r][1]);
                    }
                }
            }
            __syncthreads();                        // compute done, s_wt free
            if (t + 1 < NT) stageE(t + 1);
        }
#pragma unroll
        for (int r = 0; r < 8; ++r) {
            int d = 8 * ty + r;
            float bias = __ldg(&Eb[h * 128 + d]);
            float v0, v1, v2, v3;
            unpack2(acc[r][0], v0, v1); unpack2(acc[r][1], v2, v3);
            v0 += bias; v1 += bias; v2 += bias; v3 += bias;
            v0 = LRELU(v0); v1 = LRELU(v1); v2 = LRELU(v2); v3 = LRELU(v3);
            *(float2*)&s_seT[d * 66 + 4 * tx]     = make_float2(v0, v1);
            *(float2*)&s_seT[d * 66 + 4 * tx + 2] = make_float2(v2, v3);
        }
    }

    // ---- Phase 2a: t[n][d'] = se M^T (A from seT scalar broadcasts) -------
    {
        const int tx = tid & 31, ty = tid >> 5;     // 32 d'-quads x 8 n-groups
        ull acc[8][2] = {};
        const float* gMh = gM + (size_t)h * 128 * 128;   // transposed [d][d']
        auto stageM = [&](int t) {
            for (int idx = tid; idx < 1024; idx += 256) {
                int kk = idx >> 5, c = idx & 31;
                cp16(s2u(s_wt + kk * 132 + c * 4),
                     gMh + (size_t)(t * 32 + kk) * 128 + c * 4);
            }
            cp_commit();
        };
        stageM(0);
        for (int t = 0; t < 4; ++t) {
            cp_wait<0>(); __syncthreads();          // (also orders seT stores)
#pragma unroll
            for (int k4 = 0; k4 < 8; ++k4) {
#pragma unroll
                for (int q = 0; q < 4; ++q) {
                    const float* sa = &s_seT[(t * 32 + 4 * k4 + q) * 66 + 8 * ty];
                    ulonglong2 bb = *(const ulonglong2*)&s_wt[(4 * k4 + q) * 132 + 4 * tx];
#pragma unroll
                    for (int r = 0; r < 8; ++r) {
                        float av = sa[r];
                        ull ap = pack2(av, av);
                        acc[r][0] = fma2(ap, bb.x, acc[r][0]);
                        acc[r][1] = fma2(ap, bb.y, acc[r][1]);
                    }
                }
            }
            __syncthreads();
            if (t + 1 < 4) stageM(t + 1);
        }
#pragma unroll
        for (int r = 0; r < 8; ++r) {
            int row = 8 * ty + r;
            float v0, v1, v2, v3;
            unpack2(acc[r][0], v0, v1); unpack2(acc[r][1], v2, v3);
            *(float2*)&s_t[row * 128 + 4 * tx]     = make_float2(v0, v1);
            *(float2*)&s_t[row * 128 + 4 * tx + 2] = make_float2(v2, v3);
        }
    }

    // ---- Phase 2b: v[m][o] = lrelu(se Vw^T + Vb) ---------------------------
    {
        const int tx = tid & 15, ty = tid >> 4;     // 16 o-pairs x 16 m-groups
        ull acc[4] = {};
        const float* VwTh = gVwT + (size_t)h * 128 * 32;  // [k][o]
        auto stageV = [&](int t) {
            {
                int kk = tid >> 3, c = tid & 7;     // exactly 256 chunks
                cp16(s2u(s_wt + kk * 36 + c * 4),
                     VwTh + (size_t)(t * 32 + kk) * 32 + c * 4);
            }
            cp_commit();
        };
        stageV(0);
        for (int t = 0; t < 4; ++t) {
            cp_wait<0>(); __syncthreads();
#pragma unroll
            for (int k4 = 0; k4 < 8; ++k4) {
#pragma unroll
                for (int q = 0; q < 4; ++q) {
                    const float* sa = &s_seT[(t * 32 + 4 * k4 + q) * 66 + 4 * ty];
                    ull bb = *(const ull*)&s_wt[(4 * k4 + q) * 36 + 2 * tx];
#pragma unroll
                    for (int r = 0; r < 4; ++r) {
                        float av = sa[r];
                        acc[r] = fma2(pack2(av, av), bb, acc[r]);
                    }
                }
            }
            __syncthreads();
            if (t + 1 < 4) stageV(t + 1);
        }
        float b0 = __ldg(&Vb[h * 32 + 2 * tx]), b1 = __ldg(&Vb[h * 32 + 2 * tx + 1]);
#pragma unroll
        for (int r = 0; r < 4; ++r) {
            float v0, v1; unpack2(acc[r], v0, v1);
            v0 += b0; v1 += b1; v0 = LRELU(v0); v1 = LRELU(v1);
            *(float2*)&s_v[(4 * ty + r) * 32 + 2 * tx] = make_float2(v0, v1);
        }
    }

    // ---- c_m = se_m . a2 ----------------------------------------------------
    if (tid < 64) {
        const float* a2h = gA2 + h * 128;
        float s = 0.f;
#pragma unroll 4
        for (int d = 0; d < 128; ++d)
            s += s_seT[d * 66 + tid] * __ldg(&a2h[d]);
        s_c[tid] = s;
    }
    __syncthreads();

    // ---- Phase 3: scores = t . seT + c, softmax ----------------------------
    {
        const int tx = tid & 31, ty = tid >> 5;
        const float2 cc = *(const float2*)&s_c[2 * tx];
        ull sacc[8] = {};
#pragma unroll 4
        for (int k4 = 0; k4 < 32; ++k4) {
            float4 a[8];
#pragma unroll
            for (int r = 0; r < 8; ++r)
                a[r] = *(const float4*)&s_t[(8 * ty + r) * 128 + 4 * k4];
#pragma unroll
            for (int q = 0; q < 4; ++q) {
                ull bb = *(const ull*)&s_seT[(4 * k4 + q) * 66 + 2 * tx];
#pragma unroll
                for (int r = 0; r < 8; ++r)
                    sacc[r] = fma2(pack2((&a[r].x)[q], (&a[r].x)[q]), bb, sacc[r]);
            }
        }
        const float SCALE = 0.08838834764831845f;   // 1/sqrt(128)
        float* wg = w_out + (((size_t)h * Bb + b) * 64) * 64;
#pragma unroll
        for (int i = 0; i < 8; ++i) {
            float sc0, sc1; unpack2(sacc[i], sc0, sc1);
            sc0 = (sc0 + cc.x) * SCALE;
            sc1 = (sc1 + cc.y) * SCALE;
            float m = fmaxf(sc0, sc1);
#pragma unroll
            for (int off = 1; off < 32; off <<= 1)
                m = fmaxf(m, __shfl_xor_sync(0xffffffffu, m, off));
            sc0 = __expf(sc0 - m); sc1 = __expf(sc1 - m);
            float s = sc0 + sc1;
#pragma unroll
            for (int off = 1; off < 32; off <<= 1)
                s += __shfl_xor_sync(0xffffffffu, s, off);
            float inv = 1.0f / s;
            float2 wv = make_float2(sc0 * inv, sc1 * inv);
            int row = 8 * ty + i;
            *(float2*)&s_w[row * 64 + 2 * tx] = wv;
            *(float2*)&wg[(size_t)row * 64 + 2 * tx] = wv;
        }
    }
    __syncthreads();

    // ---- Phase 4: att = w @ v ----------------------------------------------
    {
        const int tx = tid & 15, ty = tid >> 4;
        ull aacc[4] = {};
#pragma unroll 4
        for (int k4 = 0; k4 < 16; ++k4) {
            float4 a0 = *(const float4*)&s_w[(4 * ty + 0) * 64 + 4 * k4];
            float4 a1 = *(const float4*)&s_w[(4 * ty + 1) * 64 + 4 * k4];
            float4 a2 = *(const float4*)&s_w[(4 * ty + 2) * 64 + 4 * k4];
            float4 a3 = *(const float4*)&s_w[(4 * ty + 3) * 64 + 4 * k4];
#pragma unroll
            for (int q = 0; q < 4; ++q) {
                ull bb = *(const ull*)&s_v[(4 * k4 + q) * 32 + 2 * tx];
                aacc[0] = fma2(pack2((&a0.x)[q], (&a0.x)[q]), bb, aacc[0]);
                aacc[1] = fma2(pack2((&a1.x)[q], (&a1.x)[q]), bb, aacc[1]);
                aacc[2] = fma2(pack2((&a2.x)[q], (&a2.x)[q]), bb, aacc[2]);
                aacc[3] = fma2(pack2((&a3.x)[q], (&a3.x)[q]), bb, aacc[3]);
            }
        }
#pragma unroll
        for (int i = 0; i < 4; ++i) {
            float v0, v1; unpack2(aacc[i], v0, v1);
            int row = 4 * ty + i;
            *(float2*)&x_out[((size_t)b * 64 + row) * 128 + h * 32 + 2 * tx] =
                make_float2(v0, v1);
        }
    }
}

// ---------------------------------------------------------------------------
// Final MLP + softmax policy head.
// ---------------------------------------------------------------------------
__global__ void __launch_bounds__(256)
mlp_kernel(const float* __restrict__ x,
           const float* __restrict__ F1w, const float* __restrict__ F1b,
           const float* __restrict__ F2w, const float* __restrict__ F2b,
           float* __restrict__ out)
{
    __shared__ float sF1[128 * 65];
    __shared__ float sF2[16 * 64];
    __shared__ float sB1[64];
    __shared__ float sB2[16];
    __shared__ float sx[8][2][128];

    const int tid = threadIdx.x, lane = tid & 31, warp = tid >> 5;

    for (int idx = tid; idx < 64 * 128; idx += 256) {
        int o = idx >> 7, d = idx & 127;
        sF1[d * 65 + o] = F1w[idx];
    }
    for (int idx = tid; idx < 16 * 64; idx += 256) sF2[idx] = F2w[idx];
    if (tid < 64) sB1[tid] = F1b[tid];
    if (tid < 16) sB2[tid] = F2b[tid];
    __syncthreads();

    const int NGRP = (Bb * Nn) / 2;
    for (int g = blockIdx.x * 8 + warp; g < NGRP; g += gridDim.x * 8) {
        int row0 = g * 2;
#pragma unroll
        for (int r = 0; r < 2; ++r)
            *(float4*)&sx[warp][r][lane * 4] =
                *(const float4*)&x[(size_t)(row0 + r) * 128 + lane * 4];
        __syncwarp();

        float h0[2], h1[2];
        h0[0] = h0[1] = sB1[lane];
        h1[0] = h1[1] = sB1[lane + 32];
#pragma unroll 8
        for (int d = 0; d < 128; ++d) {
            float w0 = sF1[d * 65 + lane];
            float w1 = sF1[d * 65 + 32 + lane];
#pragma unroll
            for (int r = 0; r < 2; ++r) {
                float xv = sx[warp][r][d];
                h0[r] = fmaf(xv, w0, h0[r]);
                h1[r] = fmaf(xv, w1, h1[r]);
            }
        }
#pragma unroll
        for (int r = 0; r < 2; ++r) { h0[r] = LRELU(h0[r]); h1[r] = LRELU(h1[r]); }

#pragma unroll
        for (int r = 0; r < 2; ++r) {
            float p[16];
#pragma unroll
            for (int j = 0; j < 16; ++j) {
                float t = fmaf(h0[r], sF2[j * 64 + lane],
                               h1[r] * sF2[j * 64 + 32 + lane]);
#pragma unroll
                for (int off = 16; off > 0; off >>= 1)
                    t += __shfl_xor_sync(0xffffffffu, t, off);
                p[j] = t + sB2[j];
            }
            float m = p[0];
#pragma unroll
            for (int j = 1; j < 16; ++j) m = fmaxf(m, p[j]);
            float s = 0.0f;
#pragma unroll
            for (int j = 0; j < 16; ++j) { p[j] = __expf(p[j] - m); s += p[j]; }
            float inv = 1.0f / s;
            float mine = 0.0f;
#pragma unroll
            for (int j = 0; j < 16; ++j) mine = (lane == j) ? p[j] * inv : mine;
            if (lane < 16) out[(size_t)(row0 + r) * 16 + lane] = mine;
        }
        __syncwarp();
    }
}

// ---------------------------------------------------------------------------
extern "C" void kernel_launch(void* const* d_in, const int* in_sizes, int n_in,
                              void* d_out, int out_size)
{
    const float* states = (const float*)d_in[0];
    const float* E1w = (const float*)d_in[1];  const float* E1b = (const float*)d_in[2];
    const float* K1w = (const float*)d_in[3];  const float* K1b = (const float*)d_in[4];
    const float* Q1w = (const float*)d_in[5];  const float* Q1b = (const float*)d_in[6];
    const float* V1w = (const float*)d_in[7];  const float* V1b = (const float*)d_in[8];
    const float* E2w = (const float*)d_in[9];  const float* E2b = (const float*)d_in[10];
    const float* K2w = (const float*)d_in[11]; const float* K2b = (const float*)d_in[12];
    const float* Q2w = (const float*)d_in[13]; const float* Q2b = (const float*)d_in[14];
    const float* V2w = (const float*)d_in[15]; const float* V2b = (const float*)d_in[16];
    const float* F1w = (const float*)d_in[17]; const float* F1b = (const float*)d_in[18];
    const float* F2w = (const float*)d_in[19]; const float* F2b = (const float*)d_in[20];
    (void)K1b; (void)K2b;   // K biases cancel in softmax

    float* out    = (float*)d_out;
    float* policy = out;                                      // [512,64,16]
    float* w1     = out + (size_t)Bb * Nn * FOUT;             // [4,512,64,64]
    float* w2     = w1 + (size_t)Hh * Bb * Nn * Nn;           // [4,512,64,64]

    float* x1p = nullptr; float* x2p = nullptr;
    float* Mp = nullptr;  float* a2p = nullptr; float* vtp = nullptr;
    cudaGetSymbolAddress((void**)&x1p, g_x1);
    cudaGetSymbolAddress((void**)&x2p, g_x2);
    cudaGetSymbolAddress((void**)&Mp,  g_M);
    cudaGetSymbolAddress((void**)&a2p, g_a2);
    cudaGetSymbolAddress((void**)&vtp, g_VwT);

    prep_kernel<<<dim3(Hh, 8), 256>>>(Q1w, K1w, Q1b, V1w,
                                      Mp, a2p, vtp);
    prep_kernel<<<dim3(Hh, 8), 256>>>(Q2w, K2w, Q2b, V2w,
                                      Mp + Hh * 128 * 128, a2p + Hh * 128,
                                      vtp + Hh * 128 * 32);

    const int SMEM = SMEM_FLOATS * 4;   // 102144 B -> 2 CTAs/SM
    cudaFuncSetAttribute(attn_kernel<256>, cudaFuncAttributeMaxDynamicSharedMemorySize, SMEM);
    cudaFuncSetAttribute(attn_kernel<128>, cudaFuncAttributeMaxDynamicSharedMemorySize, SMEM);

    dim3 grid(Hh, Bb);
    attn_kernel<256><<<grid, 256, SMEM>>>(states, E1w, E1b,
                                          Mp, a2p, vtp, V1b, w1, x1p);
    attn_kernel<128><<<grid, 256, SMEM>>>(x1p, E2w, E2b,
                                          Mp + Hh * 128 * 128, a2p + Hh * 128,
                                          vtp + Hh * 128 * 32, V2b, w2, x2p);
    mlp_kernel<<<512, 256>>>(x2p, F1w, F1b, F2w, F2b, policy);
}

// round 16
// speedup vs baseline: 1.1715x; 1.0051x over previous
#include <cuda_runtime.h>
#include <cstdint>

#define LRELU(v) ((v) > 0.0f ? (v) : 0.01f * (v))
using ull = unsigned long long;

static constexpr int Bb   = 512;
static constexpr int Nn   = 64;
static constexpr int Hh   = 4;
static constexpr int FOUT = 16;

// Scratch
__device__ float g_x1[(size_t)Bb * Nn * 128];
__device__ float g_x2[(size_t)Bb * Nn * 128];
__device__ float g_M  [(size_t)2 * Hh * 128 * 128];  // M^T_h: [d][d'] (pre-transposed)
__device__ float g_a2 [(size_t)2 * Hh * 128];        // a2_h = Kw^T qb
__device__ float g_VwT[(size_t)2 * Hh * 128 * 32];   // Vw^T_h: [k][o]

// ---------------------------------------------------------------------------
// Packed fp32x2 helpers
// ---------------------------------------------------------------------------
__device__ __forceinline__ ull pack2(float a, float b) {
    ull r; asm("mov.b64 %0, {%1, %2};" : "=l"(r) : "f"(a), "f"(b)); return r;
}
__device__ __forceinline__ void unpack2(ull v, float& a, float& b) {
    asm("mov.b64 {%0, %1}, %2;" : "=f"(a), "=f"(b) : "l"(v));
}
__device__ __forceinline__ ull fma2(ull a, ull b, ull c) {
    ull d; asm("fma.rn.f32x2 %0, %1, %2, %3;" : "=l"(d) : "l"(a), "l"(b), "l"(c)); return d;
}

// ---------------------------------------------------------------------------
// cp.async helpers
// ---------------------------------------------------------------------------
__device__ __forceinline__ uint32_t s2u(const void* p) {
    return (uint32_t)__cvta_generic_to_shared(p);
}
__device__ __forceinline__ void cp16(uint32_t dst, const float* src) {
    asm volatile("cp.async.cg.shared.global [%0], [%1], 16;" :: "r"(dst), "l"(src));
}
__device__ __forceinline__ void cp_commit() {
    asm volatile("cp.async.commit_group;" ::: "memory");
}
template<int N>
__device__ __forceinline__ void cp_wait() {
    asm volatile("cp.async.wait_group %0;" :: "n"(N) : "memory");
}

// ---------------------------------------------------------------------------
// Prep per head: M^T[d][d'] = sum_e Kw[e,d']*Qw[e,d];  a2[d] = sum_e Kw[e,d]*qb[e];
//                Vw^T[k][o] = Vw[o][k].
// ---------------------------------------------------------------------------
__global__ void __launch_bounds__(256)
prep_kernel(const float* __restrict__ Qw, const float* __restrict__ Kw,
            const float* __restrict__ Qb, const float* __restrict__ Vw,
            float* __restrict__ Mout, float* __restrict__ a2out,
            float* __restrict__ VwTout)
{
    const int h = blockIdx.x, slice = blockIdx.y, tid = threadIdx.x;
    const float* Qh = Qw + (size_t)h * 128 * 128;
    const float* Kh = Kw + (size_t)h * 128 * 128;
#pragma unroll
    for (int j = 0; j < 8; ++j) {
        int id = tid + 256 * j;
        int d  = 16 * slice + (id >> 7);     // warp-uniform (Q side)
        int dp = id & 127;                   // lane-consecutive (K side)
        float s = 0.f;
#pragma unroll 4
        for (int e = 0; e < 128; ++e)
            s += __ldg(&Kh[e * 128 + dp]) * __ldg(&Qh[e * 128 + d]);
        Mout[((size_t)h * 128 + d) * 128 + dp] = s;     // transposed layout
    }
    if (slice == 0 && tid < 128) {
        float s = 0.f;
#pragma unroll 4
        for (int e = 0; e < 128; ++e)
            s += __ldg(&Kh[e * 128 + tid]) * __ldg(&Qb[h * 128 + e]);
        a2out[h * 128 + tid] = s;
    }
    if (slice == 1) {
        const float* Vh = Vw + (size_t)h * 32 * 128;
        for (int idx = tid; idx < 128 * 32; idx += 256) {
            int k = idx >> 5, o = idx & 31;
            VwTout[(size_t)h * 128 * 32 + idx] = __ldg(&Vh[o * 128 + k]);
        }
    }
}

// ---------------------------------------------------------------------------
// smem layout (103.2 KB -> 2 CTAs/SM). seT stride 68 (16B-aligned rows).
// ---------------------------------------------------------------------------
static constexpr int OFF_XT  = 0;                     // [32][68]
static constexpr int OFF_SET = OFF_XT  + 32 * 68;     // [128][68]
static constexpr int OFF_T   = OFF_SET + 128 * 68;    // [64][128]
static constexpr int OFF_WT  = OFF_T   + 64 * 128;    // 128*36 staging / s_w overlay
static constexpr int OFF_V   = OFF_WT  + 128 * 36;    // [64][32]
static constexpr int OFF_C   = OFF_V   + 64 * 32;     // [64]
static constexpr int SMEM_FLOATS = OFF_C + 64;        // 25792 -> 103168 B

template<int IN_DIM>
__global__ void __launch_bounds__(256, 2)
attn_kernel(const float* __restrict__ x,
            const float* __restrict__ Ew, const float* __restrict__ Eb,
            const float* __restrict__ gM, const float* __restrict__ gA2,
            const float* __restrict__ gVwT, const float* __restrict__ Vb,
            float* __restrict__ w_out, float* __restrict__ x_out)
{
    extern __shared__ float smem[];
    float* s_xt  = smem + OFF_XT;
    float* s_seT = smem + OFF_SET;
    float* s_t   = smem + OFF_T;
    float* s_wt  = smem + OFF_WT;
    float* s_v   = smem + OFF_V;
    float* s_c   = smem + OFF_C;
    float* s_w   = s_wt;                 // overlay in phases 3/4

    const int h = blockIdx.x, b = blockIdx.y, tid = threadIdx.x;
    const float* gx  = x + (size_t)b * 64 * IN_DIM;
    const float* Ewh = Ew + (size_t)h * 128 * IN_DIM;

    // ---- Phase 1: seT[d][n] = lrelu(x Ew^T + Eb)^T ------------------------
    {
        const int tx = tid & 15, ty = tid >> 4;     // 16 n-quads x 16 d-groups
        ull acc[8][2] = {};
        float4 rx[2];
        auto ldx = [&](int t) {
#pragma unroll
            for (int j = 0; j < 2; ++j) {
                int idx = tid + 256 * j;
                rx[j] = *(const float4*)&gx[(idx >> 3) * IN_DIM + t * 32 + (idx & 7) * 4];
            }
        };
        auto stx = [&]() {
#pragma unroll
            for (int j = 0; j < 2; ++j) {
                int idx = tid + 256 * j, n = idx >> 3, c = idx & 7;
                s_xt[(c * 4 + 0) * 68 + n] = rx[j].x;
                s_xt[(c * 4 + 1) * 68 + n] = rx[j].y;
                s_xt[(c * 4 + 2) * 68 + n] = rx[j].z;
                s_xt[(c * 4 + 3) * 68 + n] = rx[j].w;
            }
        };
        auto stageE = [&](int t) {
            for (int idx = tid; idx < 1024; idx += 256) {
                int d = idx >> 3, c = idx & 7;
                cp16(s2u(s_wt + d * 36 + c * 4),
                     Ewh + (size_t)d * IN_DIM + t * 32 + c * 4);
            }
            cp_commit();
        };
        ldx(0); stageE(0);
        const int NT = IN_DIM / 32;
        for (int t = 0; t < NT; ++t) {
            cp_wait<0>(); __syncthreads();          // E tile ready, s_xt free
            stx();
            if (t + 1 < NT) ldx(t + 1);
            __syncthreads();                        // x tile visible
#pragma unroll
            for (int k4 = 0; k4 < 8; ++k4) {
                float4 a[8];
#pragma unroll
                for (int r = 0; r < 8; ++r)
                    a[r] = *(const float4*)&s_wt[(8 * ty + r) * 36 + 4 * k4];
#pragma unroll
                for (int q = 0; q < 4; ++q) {
                    ulonglong2 bb = *(const ulonglong2*)&s_xt[(4 * k4 + q) * 68 + 4 * tx];
#pragma unroll
                    for (int r = 0; r < 8; ++r) {
                        ull ap = pack2((&a[r].x)[q], (&a[r].x)[q]);
                        acc[r][0] = fma2(ap, bb.x, acc[r][0]);
                        acc[r][1] = fma2(ap, bb.y, acc[r][1]);
                    }
                }
            }
            __syncthreads();                        // compute done, s_wt free
            if (t + 1 < NT) stageE(t + 1);
        }
#pragma unroll
        for (int r = 0; r < 8; ++r) {
            int d = 8 * ty + r;
            float bias = __ldg(&Eb[h * 128 + d]);
            float v0, v1, v2, v3;
            unpack2(acc[r][0], v0, v1); unpack2(acc[r][1], v2, v3);
            v0 += bias; v1 += bias; v2 += bias; v3 += bias;
            v0 = LRELU(v0); v1 = LRELU(v1); v2 = LRELU(v2); v3 = LRELU(v3);
            *(float4*)&s_seT[d * 68 + 4 * tx] = make_float4(v0, v1, v2, v3);
        }
    }

    // ---- Phase 2a: t[n][d'] = se M^T (A via 2x LDS.128 broadcasts) --------
    {
        const int tx = tid & 31, ty = tid >> 5;     // 32 d'-quads x 8 n-groups
        ull acc[8][2] = {};
        const float* gMh = gM + (size_t)h * 128 * 128;   // transposed [d][d']
        auto stageM = [&](int t) {
            for (int idx = tid; idx < 1024; idx += 256) {
                int kk = idx >> 5, c = idx & 31;
                cp16(s2u(s_wt + kk * 132 + c * 4),
                     gMh + (size_t)(t * 32 + kk) * 128 + c * 4);
            }
            cp_commit();
        };
        stageM(0);
        for (int t = 0; t < 4; ++t) {
            cp_wait<0>(); __syncthreads();          // (also orders seT stores)
#pragma unroll
            for (int k4 = 0; k4 < 8; ++k4) {
#pragma unroll
                for (int q = 0; q < 4; ++q) {
                    const float* sa = &s_seT[(t * 32 + 4 * k4 + q) * 68 + 8 * ty];
                    float4 sa0 = *(const float4*)sa;
                    float4 sa1 = *(const float4*)(sa + 4);
                    ulonglong2 bb = *(const ulonglong2*)&s_wt[(4 * k4 + q) * 132 + 4 * tx];
#pragma unroll
                    for (int r = 0; r < 4; ++r) {
                        ull ap = pack2((&sa0.x)[r], (&sa0.x)[r]);
                        acc[r][0] = fma2(ap, bb.x, acc[r][0]);
                        acc[r][1] = fma2(ap, bb.y, acc[r][1]);
                    }
#pragma unroll
                    for (int r = 0; r < 4; ++r) {
                        ull ap = pack2((&sa1.x)[r], (&sa1.x)[r]);
                        acc[4 + r][0] = fma2(ap, bb.x, acc[4 + r][0]);
                        acc[4 + r][1] = fma2(ap, bb.y, acc[4 + r][1]);
                    }
                }
            }
            __syncthreads();
            if (t + 1 < 4) stageM(t + 1);
        }
#pragma unroll
        for (int r = 0; r < 8; ++r) {
            int row = 8 * ty + r;
            float v0, v1, v2, v3;
            unpack2(acc[r][0], v0, v1); unpack2(acc[r][1], v2, v3);
            *(float2*)&s_t[row * 128 + 4 * tx]     = make_float2(v0, v1);
            *(float2*)&s_t[row * 128 + 4 * tx + 2] = make_float2(v2, v3);
        }
    }

    // ---- Phase 2b: v[m][o] = lrelu(se Vw^T + Vb) (A via 1x LDS.128) -------
    {
        const int tx = tid & 15, ty = tid >> 4;     // 16 o-pairs x 16 m-groups
        ull acc[4] = {};
        const float* VwTh = gVwT + (size_t)h * 128 * 32;  // [k][o]
        auto stageV = [&](int t) {
            {
                int kk = tid >> 3, c = tid & 7;     // exactly 256 chunks
                cp16(s2u(s_wt + kk * 36 + c * 4),
                     VwTh + (size_t)(t * 32 + kk) * 32 + c * 4);
            }
            cp_commit();
        };
        stageV(0);
        for (int t = 0; t < 4; ++t) {
            cp_wait<0>(); __syncthreads();
#pragma unroll
            for (int k4 = 0; k4 < 8; ++k4) {
#pragma unroll
                for (int q = 0; q < 4; ++q) {
                    float4 sa = *(const float4*)&s_seT[(t * 32 + 4 * k4 + q) * 68 + 4 * ty];
                    ull bb = *(const ull*)&s_wt[(4 * k4 + q) * 36 + 2 * tx];
#pragma unroll
                    for (int r = 0; r < 4; ++r)
                        acc[r] = fma2(pack2((&sa.x)[r], (&sa.x)[r]), bb, acc[r]);
                }
            }
            __syncthreads();
            if (t + 1 < 4) stageV(t + 1);
        }
        float b0 = __ldg(&Vb[h * 32 + 2 * tx]), b1 = __ldg(&Vb[h * 32 + 2 * tx + 1]);
#pragma unroll
        for (int r = 0; r < 4; ++r) {
            float v0, v1; unpack2(acc[r], v0, v1);
            v0 += b0; v1 += b1; v0 = LRELU(v0); v1 = LRELU(v1);
            *(float2*)&s_v[(4 * ty + r) * 32 + 2 * tx] = make_float2(v0, v1);
        }
    }

    // ---- c_m = se_m . a2 ----------------------------------------------------
    if (tid < 64) {
        const float* a2h = gA2 + h * 128;
        float s = 0.f;
#pragma unroll 4
        for (int d = 0; d < 128; ++d)
            s += s_seT[d * 68 + tid] * __ldg(&a2h[d]);
        s_c[tid] = s;
    }
    __syncthreads();

    // ---- Phase 3: scores = t . seT + c, softmax ----------------------------
    {
        const int tx = tid & 31, ty = tid >> 5;
        const float2 cc = *(const float2*)&s_c[2 * tx];
        ull sacc[8] = {};
#pragma unroll 4
        for (int k4 = 0; k4 < 32; ++k4) {
            float4 a[8];
#pragma unroll
            for (int r = 0; r < 8; ++r)
                a[r] = *(const float4*)&s_t[(8 * ty + r) * 128 + 4 * k4];
#pragma unroll
            for (int q = 0; q < 4; ++q) {
                ull bb = *(const ull*)&s_seT[(4 * k4 + q) * 68 + 2 * tx];
#pragma unroll
                for (int r = 0; r < 8; ++r)
                    sacc[r] = fma2(pack2((&a[r].x)[q], (&a[r].x)[q]), bb, sacc[r]);
            }
        }
        const float SCALE = 0.08838834764831845f;   // 1/sqrt(128)
        float* wg = w_out + (((size_t)h * Bb + b) * 64) * 64;
#pragma unroll
        for (int i = 0; i < 8; ++i) {
            float sc0, sc1; unpack2(sacc[i], sc0, sc1);
            sc0 = (sc0 + cc.x) * SCALE;
            sc1 = (sc1 + cc.y) * SCALE;
            float m = fmaxf(sc0, sc1);
#pragma unroll
            for (int off = 1; off < 32; off <<= 1)
                m = fmaxf(m, __shfl_xor_sync(0xffffffffu, m, off));
            sc0 = __expf(sc0 - m); sc1 = __expf(sc1 - m);
            float s = sc0 + sc1;
#pragma unroll
            for (int off = 1; off < 32; off <<= 1)
                s += __shfl_xor_sync(0xffffffffu, s, off);
            float inv = 1.0f / s;
            float2 wv = make_float2(sc0 * inv, sc1 * inv);
            int row = 8 * ty + i;
            *(float2*)&s_w[row * 64 + 2 * tx] = wv;
            *(float2*)&wg[(size_t)row * 64 + 2 * tx] = wv;
        }
    }
    __syncthreads();

    // ---- Phase 4: att = w @ v ----------------------------------------------
    {
        const int tx = tid & 15, ty = tid >> 4;
        ull aacc[4] = {};
#pragma unroll 4
        for (int k4 = 0; k4 < 16; ++k4) {
            float4 a0 = *(const float4*)&s_w[(4 * ty + 0) * 64 + 4 * k4];
            float4 a1 = *(const float4*)&s_w[(4 * ty + 1) * 64 + 4 * k4];
            float4 a2 = *(const float4*)&s_w[(4 * ty + 2) * 64 + 4 * k4];
            float4 a3 = *(const float4*)&s_w[(4 * ty + 3) * 64 + 4 * k4];
#pragma unroll
            for (int q = 0; q < 4; ++q) {
                ull bb = *(const ull*)&s_v[(4 * k4 + q) * 32 + 2 * tx];
                aacc[0] = fma2(pack2((&a0.x)[q], (&a0.x)[q]), bb, aacc[0]);
                aacc[1] = fma2(pack2((&a1.x)[q], (&a1.x)[q]), bb, aacc[1]);
                aacc[2] = fma2(pack2((&a2.x)[q], (&a2.x)[q]), bb, aacc[2]);
                aacc[3] = fma2(pack2((&a3.x)[q], (&a3.x)[q]), bb, aacc[3]);
            }
        }
#pragma unroll
        for (int i = 0; i < 4; ++i) {
            float v0, v1; unpack2(aacc[i], v0, v1);
            int row = 4 * ty + i;
            *(float2*)&x_out[((size_t)b * 64 + row) * 128 + h * 32 + 2 * tx] =
                make_float2(v0, v1);
        }
    }
}

// ---------------------------------------------------------------------------
// Final MLP + softmax policy head.
// ---------------------------------------------------------------------------
__global__ void __launch_bounds__(256)
mlp_kernel(const float* __restrict__ x,
           const float* __restrict__ F1w, const float* __restrict__ F1b,
           const float* __restrict__ F2w, const float* __restrict__ F2b,
           float* __restrict__ out)
{
    __shared__ float sF1[128 * 65];
    __shared__ float sF2[16 * 64];
    __shared__ float sB1[64];
    __shared__ float sB2[16];
    __shared__ float sx[8][2][128];

    const int tid = threadIdx.x, lane = tid & 31, warp = tid >> 5;

    for (int idx = tid; idx < 64 * 128; idx += 256) {
        int o = idx >> 7, d = idx & 127;
        sF1[d * 65 + o] = F1w[idx];
    }
    for (int idx = tid; idx < 16 * 64; idx += 256) sF2[idx] = F2w[idx];
    if (tid < 64) sB1[tid] = F1b[tid];
    if (tid < 16) sB2[tid] = F2b[tid];
    __syncthreads();

    const int NGRP = (Bb * Nn) / 2;
    for (int g = blockIdx.x * 8 + warp; g < NGRP; g += gridDim.x * 8) {
        int row0 = g * 2;
#pragma unroll
        for (int r = 0; r < 2; ++r)
            *(float4*)&sx[warp][r][lane * 4] =
                *(const float4*)&x[(size_t)(row0 + r) * 128 + lane * 4];
        __syncwarp();

        float h0[2], h1[2];
        h0[0] = h0[1] = sB1[lane];
        h1[0] = h1[1] = sB1[lane + 32];
#pragma unroll 8
        for (int d = 0; d < 128; ++d) {
            float w0 = sF1[d * 65 + lane];
            float w1 = sF1[d * 65 + 32 + lane];
#pragma unroll
            for (int r = 0; r < 2; ++r) {
                float xv = sx[warp][r][d];
                h0[r] = fmaf(xv, w0, h0[r]);
                h1[r] = fmaf(xv, w1, h1[r]);
            }
        }
#pragma unroll
        for (int r = 0; r < 2; ++r) { h0[r] = LRELU(h0[r]); h1[r] = LRELU(h1[r]); }

#pragma unroll
        for (int r = 0; r < 2; ++r) {
            float p[16];
#pragma unroll
            for (int j = 0; j < 16; ++j) {
                float t = fmaf(h0[r], sF2[j * 64 + lane],
                               h1[r] * sF2[j * 64 + 32 + lane]);
#pragma unroll
                for (int off = 16; off > 0; off >>= 1)
                    t += __shfl_xor_sync(0xffffffffu, t, off);
                p[j] = t + sB2[j];
            }
            float m = p[0];
#pragma unroll
            for (int j = 1; j < 16; ++j) m = fmaxf(m, p[j]);
            float s = 0.0f;
#pragma unroll
            for (int j = 0; j < 16; ++j) { p[j] = __expf(p[j] - m); s += p[j]; }
            float inv = 1.0f / s;
            float mine = 0.0f;
#pragma unroll
            for (int j = 0; j < 16; ++j) mine = (lane == j) ? p[j] * inv : mine;
            if (lane < 16) out[(size_t)(row0 + r) * 16 + lane] = mine;
        }
        __syncwarp();
    }
}

// ---------------------------------------------------------------------------
extern "C" void kernel_launch(void* const* d_in, const int* in_sizes, int n_in,
                              void* d_out, int out_size)
{
    const float* states = (const float*)d_in[0];
    const float* E1w = (const float*)d_in[1];  const float* E1b = (const float*)d_in[2];
    const float* K1w = (const float*)d_in[3];  const float* K1b = (const float*)d_in[4];
    const float* Q1w = (const float*)d_in[5];  const float* Q1b = (const float*)d_in[6];
    const float* V1w = (const float*)d_in[7];  const float* V1b = (const float*)d_in[8];
    const float* E2w = (const float*)d_in[9];  const float* E2b = (const float*)d_in[10];
    const float* K2w = (const float*)d_in[11]; const float* K2b = (const float*)d_in[12];
    const float* Q2w = (const float*)d_in[13]; const float* Q2b = (const float*)d_in[14];
    const float* V2w = (const float*)d_in[15]; const float* V2b = (const float*)d_in[16];
    const float* F1w = (const float*)d_in[17]; const float* F1b = (const float*)d_in[18];
    const float* F2w = (const float*)d_in[19]; const float* F2b = (const float*)d_in[20];
    (void)K1b; (void)K2b;   // K biases cancel in softmax

    float* out    = (float*)d_out;
    float* policy = out;                                      // [512,64,16]
    float* w1     = out + (size_t)Bb * Nn * FOUT;             // [4,512,64,64]
    float* w2     = w1 + (size_t)Hh * Bb * Nn * Nn;           // [4,512,64,64]

    float* x1p = nullptr; float* x2p = nullptr;
    float* Mp = nullptr;  float* a2p = nullptr; float* vtp = nullptr;
    cudaGetSymbolAddress((void**)&x1p, g_x1);
    cudaGetSymbolAddress((void**)&x2p, g_x2);
    cudaGetSymbolAddress((void**)&Mp,  g_M);
    cudaGetSymbolAddress((void**)&a2p, g_a2);
    cudaGetSymbolAddress((void**)&vtp, g_VwT);

    prep_kernel<<<dim3(Hh, 8), 256>>>(Q1w, K1w, Q1b, V1w,
                                      Mp, a2p, vtp);
    prep_kernel<<<dim3(Hh, 8), 256>>>(Q2w, K2w, Q2b, V2w,
                                      Mp + Hh * 128 * 128, a2p + Hh * 128,
                                      vtp + Hh * 128 * 32);

    const int SMEM = SMEM_FLOATS * 4;   // 103168 B -> 2 CTAs/SM
    cudaFuncSetAttribute(attn_kernel<256>, cudaFuncAttributeMaxDynamicSharedMemorySize, SMEM);
    cudaFuncSetAttribute(attn_kernel<128>, cudaFuncAttributeMaxDynamicSharedMemorySize, SMEM);

    dim3 grid(Hh, Bb);
    attn_kernel<256><<<grid, 256, SMEM>>>(states, E1w, E1b,
                                          Mp, a2p, vtp, V1b, w1, x1p);
    attn_kernel<128><<<grid, 256, SMEM>>>(x1p, E2w, E2b,
                                          Mp + Hh * 128 * 128, a2p + Hh * 128,
                                          vtp + Hh * 128 * 32, V2b, w2, x2p);
    mlp_kernel<<<512, 256>>>(x2p, F1w, F1b, F2w, F2b, policy);
}